// round 13
// baseline (speedup 1.0000x reference)
#include <cuda_runtime.h>
#include <cuda_fp16.h>
#include <cstdint>

#define NNETS_MAX 3000000
#define MAX_RBLOCKS 4096

// Per-net extremes, one 8-byte word per net:
//   g_ext[net].x = f16x2( xmax,  ymax  )
//   g_ext[net].y = f16x2( -xmin, -ymin )
// Identity/reset pattern: byte 0xFB -> each half = 0xFBFB = -65367 (finite f16),
// below any real coordinate => valid identity for max, settable by memset.
// word == 0xFBFBFBFB <=> net untouched.
__device__ uint2 g_ext[NNETS_MAX];

// last-block finalize state (BSS zero-init; counter self-resets each call)
__device__ float    g_partials[MAX_RBLOCKS];
__device__ unsigned g_done_count;

#define SENTINEL 0xFBFBFBFBu

// 64-bit vector reduction: componentwise max on 4 packed halves.
static __device__ __forceinline__ void red_max_v2f16x2(uint2* addr, unsigned w0, unsigned w1) {
    asm volatile("red.global.max.noftz.v2.f16x2 [%0], {%1, %2};"
                 :: "l"(addr), "r"(w0), "r"(w1) : "memory");
}

// pack (x,y) once; negate the packed pair with one fp16 op
static __device__ __forceinline__ void pack_xy(float x, float y, unsigned& w0, unsigned& w1) {
    __half2 h = __floats2half2_rn(x, y);
    __half2 hn = __hneg2(h);
    w0 = *reinterpret_cast<unsigned*>(&h);
    w1 = *reinterpret_cast<unsigned*>(&hn);
}

// 4 pins per thread, ONE vector atomic per pin.
__global__ void pin_kernel4(const float4* __restrict__ x4,
                            const float4* __restrict__ y4,
                            const int4* __restrict__ net4,
                            int n4) {
    int i = blockIdx.x * blockDim.x + threadIdx.x;
    if (i >= n4) return;
    float4 x = __ldcs(x4 + i);
    float4 y = __ldcs(y4 + i);
    int4  nt = __ldcs(net4 + i);

    unsigned w0, w1;
    pack_xy(x.x, y.x, w0, w1); red_max_v2f16x2(g_ext + (unsigned)nt.x, w0, w1);
    pack_xy(x.y, y.y, w0, w1); red_max_v2f16x2(g_ext + (unsigned)nt.y, w0, w1);
    pack_xy(x.z, y.z, w0, w1); red_max_v2f16x2(g_ext + (unsigned)nt.z, w0, w1);
    pack_xy(x.w, y.w, w0, w1); red_max_v2f16x2(g_ext + (unsigned)nt.w, w0, w1);
}

__global__ void pin_kernel_tail(const float* __restrict__ pos,
                                const int* __restrict__ p2n,
                                int start, int npins) {
    int i = start + blockIdx.x * blockDim.x + threadIdx.x;
    if (i >= npins) return;
    unsigned w0, w1;
    pack_xy(__ldcs(pos + i), __ldcs(pos + npins + i), w0, w1);
    red_max_v2f16x2(g_ext + (unsigned)__ldcs(p2n + i), w0, w1);
}

// net term: (xmax + (-xmin)) + (ymax + (-ymin)) via one packed half2 add
static __device__ __forceinline__ float net_term(unsigned ex, unsigned ey, int m) {
    __half2 a = *reinterpret_cast<__half2*>(&ex);
    __half2 b = *reinterpret_cast<__half2*>(&ey);
    __half2 sp = __hadd2(a, b);          // (xmax-xmin, ymax-ymin)
    float2 f = __half22float2(sp);
    float v = f.x + f.y;
    return (m && ex != SENTINEL) ? v : 0.0f;
}

// mask is int32 (harness converts bool -> int32). Each thread: 8 nets.
// Last-arriving block sums the per-block partials and writes out directly
// (no out-memset node needed; counter self-resets for graph replay).
__global__ void reduce_kernel(const int* __restrict__ mask,
                              float* __restrict__ out, int nnets) {
    int t = blockIdx.x * blockDim.x + threadIdx.x;
    int n0 = t * 8;
    float s = 0.0f;
    if (n0 + 7 < nnets) {
        uint4 e01 = __ldcs(reinterpret_cast<const uint4*>(g_ext + n0));
        uint4 e23 = __ldcs(reinterpret_cast<const uint4*>(g_ext + n0 + 2));
        uint4 e45 = __ldcs(reinterpret_cast<const uint4*>(g_ext + n0 + 4));
        uint4 e67 = __ldcs(reinterpret_cast<const uint4*>(g_ext + n0 + 6));
        int4  m0  = __ldcs(reinterpret_cast<const int4*>(mask + n0));
        int4  m1  = __ldcs(reinterpret_cast<const int4*>(mask + n0 + 4));
        s += net_term(e01.x, e01.y, m0.x);
        s += net_term(e01.z, e01.w, m0.y);
        s += net_term(e23.x, e23.y, m0.z);
        s += net_term(e23.z, e23.w, m0.w);
        s += net_term(e45.x, e45.y, m1.x);
        s += net_term(e45.z, e45.w, m1.y);
        s += net_term(e67.x, e67.y, m1.z);
        s += net_term(e67.z, e67.w, m1.w);
    } else if (n0 < nnets) {
        for (int j = n0; j < nnets; j++) {
            uint2 ej = g_ext[j];
            s += net_term(ej.x, ej.y, mask[j]);
        }
    }
    // intra-block reduce
    #pragma unroll
    for (int o = 16; o > 0; o >>= 1)
        s += __shfl_down_sync(0xFFFFFFFFu, s, o);
    __shared__ float ws[32];
    __shared__ bool  is_last;
    int lane = threadIdx.x & 31;
    int w = threadIdx.x >> 5;
    if (lane == 0) ws[w] = s;
    __syncthreads();
    if (w == 0) {
        int nw = (blockDim.x + 31) >> 5;
        s = (lane < nw) ? ws[lane] : 0.0f;
        #pragma unroll
        for (int o = 16; o > 0; o >>= 1)
            s += __shfl_down_sync(0xFFFFFFFFu, s, o);
        if (lane == 0) {
            g_partials[blockIdx.x] = s;
            __threadfence();
            unsigned prev = atomicAdd(&g_done_count, 1u);
            is_last = (prev == gridDim.x - 1);
        }
    }
    __syncthreads();

    // last block: sum partials, write result, reset counter for next replay
    if (is_last) {
        float acc = 0.0f;
        for (int i = threadIdx.x; i < gridDim.x; i += blockDim.x)
            acc += g_partials[i];
        #pragma unroll
        for (int o = 16; o > 0; o >>= 1)
            acc += __shfl_down_sync(0xFFFFFFFFu, acc, o);
        if (lane == 0) ws[w] = acc;
        __syncthreads();
        if (w == 0) {
            int nw = (blockDim.x + 31) >> 5;
            acc = (lane < nw) ? ws[lane] : 0.0f;
            #pragma unroll
            for (int o = 16; o > 0; o >>= 1)
                acc += __shfl_down_sync(0xFFFFFFFFu, acc, o);
            if (lane == 0) {
                *out = acc;
                g_done_count = 0;   // reset for next graph replay
            }
        }
    }
}

extern "C" void kernel_launch(void* const* d_in, const int* in_sizes, int n_in,
                              void* d_out, int out_size) {
    const float* pos = (const float*)d_in[0];
    const int* p2n   = (const int*)d_in[1];
    const int* mask  = (const int*)d_in[2];
    float* out = (float*)d_out;

    const int npins = in_sizes[0] / 2;
    const int nnets = in_sizes[2];

    // reset scratch to the 0xFB identity pattern (single memset node)
    void* ext_ptr = nullptr;
    cudaGetSymbolAddress(&ext_ptr, g_ext);
    cudaMemsetAsync(ext_ptr, 0xFB, (size_t)nnets * sizeof(uint2));

    // pin scatter (4-wide main + scalar tail; tail never launches if npins%4==0)
    {
        int n4 = npins / 4;
        if (n4 > 0) {
            pin_kernel4<<<(n4 + 255) / 256, 256>>>(
                (const float4*)pos,
                (const float4*)(pos + npins),
                (const int4*)p2n,
                n4);
        }
        int rem = npins - n4 * 4;
        if (rem > 0) {
            pin_kernel_tail<<<(rem + 255) / 256, 256>>>(pos, p2n, n4 * 4, npins);
        }
    }

    // per-net HPWL + masked sum with in-kernel finalize
    {
        int nt = (nnets + 7) / 8;
        int blocks = (nt + 255) / 256;
        if (blocks > MAX_RBLOCKS) blocks = MAX_RBLOCKS;  // safety (1465 expected)
        reduce_kernel<<<blocks, 256>>>(mask, out, nnets);
    }
}

// round 14
// speedup vs baseline: 1.0402x; 1.0402x over previous
#include <cuda_runtime.h>
#include <cuda_fp16.h>
#include <cstdint>

#define NNETS_MAX 3000000

// Per-net extremes, one 8-byte word per net:
//   g_ext[net].x = f16x2( xmax,  ymax  )
//   g_ext[net].y = f16x2( -xmin, -ymin )
// Identity/reset pattern: byte 0xFB -> each half = 0xFBFB = -65367 (finite f16),
// below any real coordinate => valid identity for max, settable by memset.
// word == 0xFBFBFBFB <=> net untouched.
__device__ uint2 g_ext[NNETS_MAX];

#define SENTINEL 0xFBFBFBFBu

// 64-bit vector reduction: componentwise max on 4 packed halves.
static __device__ __forceinline__ void red_max_v2f16x2(uint2* addr, unsigned w0, unsigned w1) {
    asm volatile("red.global.max.noftz.v2.f16x2 [%0], {%1, %2};"
                 :: "l"(addr), "r"(w0), "r"(w1) : "memory");
}

// pack (x,y) once; negate the packed pair with one fp16 op
static __device__ __forceinline__ void pack_xy(float x, float y, unsigned& w0, unsigned& w1) {
    __half2 h = __floats2half2_rn(x, y);
    __half2 hn = __hneg2(h);
    w0 = *reinterpret_cast<unsigned*>(&h);
    w1 = *reinterpret_cast<unsigned*>(&hn);
}

// 4 pins per thread, ONE vector atomic per pin. Triggers PDL early so the
// reduce kernel can begin its (scatter-independent) mask loads during the
// scatter's last wave; the reduce's griddepcontrol.wait still guarantees it
// sees every RED.
__global__ void pin_kernel4(const float4* __restrict__ x4,
                            const float4* __restrict__ y4,
                            const int4* __restrict__ net4,
                            int n4) {
    cudaTriggerProgrammaticLaunchCompletion();
    int i = blockIdx.x * blockDim.x + threadIdx.x;
    if (i >= n4) return;
    float4 x = __ldcs(x4 + i);
    float4 y = __ldcs(y4 + i);
    int4  nt = __ldcs(net4 + i);

    unsigned w0, w1;
    pack_xy(x.x, y.x, w0, w1); red_max_v2f16x2(g_ext + (unsigned)nt.x, w0, w1);
    pack_xy(x.y, y.y, w0, w1); red_max_v2f16x2(g_ext + (unsigned)nt.y, w0, w1);
    pack_xy(x.z, y.z, w0, w1); red_max_v2f16x2(g_ext + (unsigned)nt.z, w0, w1);
    pack_xy(x.w, y.w, w0, w1); red_max_v2f16x2(g_ext + (unsigned)nt.w, w0, w1);
}

__global__ void pin_kernel_tail(const float* __restrict__ pos,
                                const int* __restrict__ p2n,
                                int start, int npins) {
    cudaTriggerProgrammaticLaunchCompletion();
    int i = start + blockIdx.x * blockDim.x + threadIdx.x;
    if (i >= npins) return;
    unsigned w0, w1;
    pack_xy(__ldcs(pos + i), __ldcs(pos + npins + i), w0, w1);
    red_max_v2f16x2(g_ext + (unsigned)__ldcs(p2n + i), w0, w1);
}

// net term: (xmax + (-xmin)) + (ymax + (-ymin)) via one packed half2 add
static __device__ __forceinline__ float net_term(unsigned ex, unsigned ey, int m) {
    __half2 a = *reinterpret_cast<__half2*>(&ex);
    __half2 b = *reinterpret_cast<__half2*>(&ey);
    __half2 sp = __hadd2(a, b);          // (xmax-xmin, ymax-ymin)
    float2 f = __half22float2(sp);
    float v = f.x + f.y;
    return (m && ex != SENTINEL) ? v : 0.0f;
}

// mask is int32 (harness converts bool -> int32). Each thread: 8 nets.
// PDL secondary: loads the mask (independent of the scatter) BEFORE waiting
// on the grid dependency, then reads g_ext once the scatter is fully visible.
__global__ void reduce_kernel(const int* __restrict__ mask,
                              float* __restrict__ out, int nnets) {
    int t = blockIdx.x * blockDim.x + threadIdx.x;
    int n0 = t * 8;
    float s = 0.0f;
    if (n0 + 7 < nnets) {
        // pre-dependency work: mask loads overlap the scatter's tail
        int4 m0 = __ldcs(reinterpret_cast<const int4*>(mask + n0));
        int4 m1 = __ldcs(reinterpret_cast<const int4*>(mask + n0 + 4));
        cudaGridDependencySynchronize();
        uint4 e01 = __ldcs(reinterpret_cast<const uint4*>(g_ext + n0));
        uint4 e23 = __ldcs(reinterpret_cast<const uint4*>(g_ext + n0 + 2));
        uint4 e45 = __ldcs(reinterpret_cast<const uint4*>(g_ext + n0 + 4));
        uint4 e67 = __ldcs(reinterpret_cast<const uint4*>(g_ext + n0 + 6));
        s += net_term(e01.x, e01.y, m0.x);
        s += net_term(e01.z, e01.w, m0.y);
        s += net_term(e23.x, e23.y, m0.z);
        s += net_term(e23.z, e23.w, m0.w);
        s += net_term(e45.x, e45.y, m1.x);
        s += net_term(e45.z, e45.w, m1.y);
        s += net_term(e67.x, e67.y, m1.z);
        s += net_term(e67.z, e67.w, m1.w);
    } else {
        cudaGridDependencySynchronize();
        if (n0 < nnets) {
            for (int j = n0; j < nnets; j++) {
                uint2 ej = g_ext[j];
                s += net_term(ej.x, ej.y, mask[j]);
            }
        }
    }
    // intra-warp reduce
    #pragma unroll
    for (int o = 16; o > 0; o >>= 1)
        s += __shfl_down_sync(0xFFFFFFFFu, s, o);
    __shared__ float ws[32];
    int lane = threadIdx.x & 31;
    int w = threadIdx.x >> 5;
    if (lane == 0) ws[w] = s;
    __syncthreads();
    if (w == 0) {
        int nw = (blockDim.x + 31) >> 5;
        s = (lane < nw) ? ws[lane] : 0.0f;
        #pragma unroll
        for (int o = 16; o > 0; o >>= 1)
            s += __shfl_down_sync(0xFFFFFFFFu, s, o);
        if (lane == 0) atomicAdd(out, s);
    }
}

extern "C" void kernel_launch(void* const* d_in, const int* in_sizes, int n_in,
                              void* d_out, int out_size) {
    const float* pos = (const float*)d_in[0];
    const int* p2n   = (const int*)d_in[1];
    const int* mask  = (const int*)d_in[2];
    float* out = (float*)d_out;

    const int npins = in_sizes[0] / 2;
    const int nnets = in_sizes[2];

    // reset: output accumulator to 0, scratch to the 0xFB identity pattern
    cudaMemsetAsync(out, 0, sizeof(float));
    void* ext_ptr = nullptr;
    cudaGetSymbolAddress(&ext_ptr, g_ext);
    cudaMemsetAsync(ext_ptr, 0xFB, (size_t)nnets * sizeof(uint2));

    // pin scatter (4-wide main + scalar tail; tail never launches for npins%4==0)
    {
        int n4 = npins / 4;
        if (n4 > 0) {
            pin_kernel4<<<(n4 + 255) / 256, 256>>>(
                (const float4*)pos,
                (const float4*)(pos + npins),
                (const int4*)p2n,
                n4);
        }
        int rem = npins - n4 * 4;
        if (rem > 0) {
            pin_kernel_tail<<<(rem + 255) / 256, 256>>>(pos, p2n, n4 * 4, npins);
        }
    }

    // per-net HPWL + masked sum — PDL secondary of the scatter
    {
        int nt = (nnets + 7) / 8;
        int blocks = (nt + 255) / 256;

        cudaLaunchConfig_t cfg = {};
        cfg.gridDim = dim3(blocks);
        cfg.blockDim = dim3(256);
        cfg.dynamicSmemBytes = 0;
        cfg.stream = 0;
        cudaLaunchAttribute attrs[1];
        attrs[0].id = cudaLaunchAttributeProgrammaticStreamSerialization;
        attrs[0].val.programmaticStreamSerializationAllowed = 1;
        cfg.attrs = attrs;
        cfg.numAttrs = 1;
        cudaLaunchKernelEx(&cfg, reduce_kernel, mask, out, nnets);
    }
}

// round 15
// speedup vs baseline: 1.0525x; 1.0119x over previous
#include <cuda_runtime.h>
#include <cuda_fp16.h>
#include <cstdint>

#define NNETS_MAX 3000000

// Per-net extremes, one 8-byte word per net:
//   g_ext[net].x = f16x2( xmax,  ymax  )
//   g_ext[net].y = f16x2( -xmin, -ymin )
// Reset value: each half = 0xFBFB = -65367 (finite f16), below any real
// coordinate => valid identity for max. word == 0xFBFBFBFB <=> net untouched.
__device__ uint2 g_ext[NNETS_MAX];

#define SENTINEL 0xFBFBFBFBu

// 64-bit vector reduction: componentwise max on 4 packed halves.
static __device__ __forceinline__ void red_max_v2f16x2(uint2* addr, unsigned w0, unsigned w1) {
    asm volatile("red.global.max.noftz.v2.f16x2 [%0], {%1, %2};"
                 :: "l"(addr), "r"(w0), "r"(w1) : "memory");
}

// pack (x,y) once; negate the packed pair with one fp16 op
static __device__ __forceinline__ void pack_xy(float x, float y, unsigned& w0, unsigned& w1) {
    __half2 h = __floats2half2_rn(x, y);
    __half2 hn = __hneg2(h);
    w0 = *reinterpret_cast<unsigned*>(&h);
    w1 = *reinterpret_cast<unsigned*>(&hn);
}

// PDL primary: reset scratch to sentinel + zero the accumulator.
// Triggers early so the scatter's CTAs can launch and begin their
// (reset-independent) input loads under this kernel's tail.
__global__ void __launch_bounds__(256)
init_kernel(float* __restrict__ out, int nnets) {
    cudaTriggerProgrammaticLaunchCompletion();
    int tid = blockIdx.x * blockDim.x + threadIdx.x;
    if (tid == 0) *out = 0.0f;
    const uint4 fb = make_uint4(SENTINEL, SENTINEL, SENTINEL, SENTINEL);
    uint4* e4 = reinterpret_cast<uint4*>(g_ext);
    int ne4 = nnets / 2;                 // one uint4 = 2 nets
    int i0 = tid * 2;
    if (i0 + 1 < ne4) {
        __stcs(e4 + i0, fb);
        __stcs(e4 + i0 + 1, fb);
    } else if (i0 < ne4) {
        __stcs(e4 + i0, fb);
    }
    if ((nnets & 1) && tid == 0)
        g_ext[nnets - 1] = make_uint2(SENTINEL, SENTINEL);
}

// PDL secondary of init / primary of reduce.
// Pre-sync: stream the inputs (independent of the reset).
// Post-sync: issue ONE vector atomic per pin.
__global__ void __launch_bounds__(256)
pin_kernel4(const float4* __restrict__ x4,
            const float4* __restrict__ y4,
            const int4* __restrict__ net4,
            int n4) {
    cudaTriggerProgrammaticLaunchCompletion();
    int i = blockIdx.x * blockDim.x + threadIdx.x;
    if (i >= n4) {
        cudaGridDependencySynchronize();
        return;
    }
    float4 x = __ldcs(x4 + i);
    float4 y = __ldcs(y4 + i);
    int4  nt = __ldcs(net4 + i);
    unsigned w0a, w1a, w0b, w1b, w0c, w1c, w0d, w1d;
    pack_xy(x.x, y.x, w0a, w1a);
    pack_xy(x.y, y.y, w0b, w1b);
    pack_xy(x.z, y.z, w0c, w1c);
    pack_xy(x.w, y.w, w0d, w1d);
    cudaGridDependencySynchronize();   // reset must be visible before REDs
    red_max_v2f16x2(g_ext + (unsigned)nt.x, w0a, w1a);
    red_max_v2f16x2(g_ext + (unsigned)nt.y, w0b, w1b);
    red_max_v2f16x2(g_ext + (unsigned)nt.z, w0c, w1c);
    red_max_v2f16x2(g_ext + (unsigned)nt.w, w0d, w1d);
}

__global__ void pin_kernel_tail(const float* __restrict__ pos,
                                const int* __restrict__ p2n,
                                int start, int npins) {
    cudaTriggerProgrammaticLaunchCompletion();
    int i = start + blockIdx.x * blockDim.x + threadIdx.x;
    cudaGridDependencySynchronize();
    if (i >= npins) return;
    unsigned w0, w1;
    pack_xy(__ldcs(pos + i), __ldcs(pos + npins + i), w0, w1);
    red_max_v2f16x2(g_ext + (unsigned)__ldcs(p2n + i), w0, w1);
}

// net term: (xmax + (-xmin)) + (ymax + (-ymin)) via one packed half2 add
static __device__ __forceinline__ float net_term(unsigned ex, unsigned ey, int m) {
    __half2 a = *reinterpret_cast<__half2*>(&ex);
    __half2 b = *reinterpret_cast<__half2*>(&ey);
    __half2 sp = __hadd2(a, b);          // (xmax-xmin, ymax-ymin)
    float2 f = __half22float2(sp);
    float v = f.x + f.y;
    return (m && ex != SENTINEL) ? v : 0.0f;
}

// mask is int32 (harness converts bool -> int32). Each thread: 8 nets.
// PDL secondary: mask loads (scatter-independent) before the dependency wait.
__global__ void reduce_kernel(const int* __restrict__ mask,
                              float* __restrict__ out, int nnets) {
    int t = blockIdx.x * blockDim.x + threadIdx.x;
    int n0 = t * 8;
    float s = 0.0f;
    if (n0 + 7 < nnets) {
        int4 m0 = __ldcs(reinterpret_cast<const int4*>(mask + n0));
        int4 m1 = __ldcs(reinterpret_cast<const int4*>(mask + n0 + 4));
        cudaGridDependencySynchronize();
        uint4 e01 = __ldcs(reinterpret_cast<const uint4*>(g_ext + n0));
        uint4 e23 = __ldcs(reinterpret_cast<const uint4*>(g_ext + n0 + 2));
        uint4 e45 = __ldcs(reinterpret_cast<const uint4*>(g_ext + n0 + 4));
        uint4 e67 = __ldcs(reinterpret_cast<const uint4*>(g_ext + n0 + 6));
        s += net_term(e01.x, e01.y, m0.x);
        s += net_term(e01.z, e01.w, m0.y);
        s += net_term(e23.x, e23.y, m0.z);
        s += net_term(e23.z, e23.w, m0.w);
        s += net_term(e45.x, e45.y, m1.x);
        s += net_term(e45.z, e45.w, m1.y);
        s += net_term(e67.x, e67.y, m1.z);
        s += net_term(e67.z, e67.w, m1.w);
    } else {
        cudaGridDependencySynchronize();
        if (n0 < nnets) {
            for (int j = n0; j < nnets; j++) {
                uint2 ej = g_ext[j];
                s += net_term(ej.x, ej.y, mask[j]);
            }
        }
    }
    // intra-warp reduce
    #pragma unroll
    for (int o = 16; o > 0; o >>= 1)
        s += __shfl_down_sync(0xFFFFFFFFu, s, o);
    __shared__ float ws[32];
    int lane = threadIdx.x & 31;
    int w = threadIdx.x >> 5;
    if (lane == 0) ws[w] = s;
    __syncthreads();
    if (w == 0) {
        int nw = (blockDim.x + 31) >> 5;
        s = (lane < nw) ? ws[lane] : 0.0f;
        #pragma unroll
        for (int o = 16; o > 0; o >>= 1)
            s += __shfl_down_sync(0xFFFFFFFFu, s, o);
        if (lane == 0) atomicAdd(out, s);
    }
}

static void launch_pdl(const void* func, int blocks, int threads, void** args) {
    cudaLaunchConfig_t cfg = {};
    cfg.gridDim = dim3(blocks);
    cfg.blockDim = dim3(threads);
    cfg.dynamicSmemBytes = 0;
    cfg.stream = 0;
    cudaLaunchAttribute attrs[1];
    attrs[0].id = cudaLaunchAttributeProgrammaticStreamSerialization;
    attrs[0].val.programmaticStreamSerializationAllowed = 1;
    cfg.attrs = attrs;
    cfg.numAttrs = 1;
    cudaLaunchKernelExC(&cfg, func, args);
}

extern "C" void kernel_launch(void* const* d_in, const int* in_sizes, int n_in,
                              void* d_out, int out_size) {
    const float* pos = (const float*)d_in[0];
    const int* p2n   = (const int*)d_in[1];
    const int* mask  = (const int*)d_in[2];
    float* out = (float*)d_out;

    int npins = in_sizes[0] / 2;
    int nnets = in_sizes[2];

    // Phase 1: reset (kernel so the scatter can PDL-overlap it)
    {
        int ne4 = nnets / 2;
        int nt = (ne4 + 1) / 2;     // 2 uint4 per thread
        int blocks = (nt + 255) / 256;
        void* args[] = { (void*)&out, (void*)&nnets };
        // plain launch (first node)
        cudaLaunchKernel((const void*)init_kernel, dim3(blocks), dim3(256), args, 0, 0);
    }

    // Phase 2: pin scatter — PDL secondary (pre-loads inputs)
    {
        int n4 = npins / 4;
        if (n4 > 0) {
            const float4* x4  = (const float4*)pos;
            const float4* y4  = (const float4*)(pos + npins);
            const int4*   nt4 = (const int4*)p2n;
            void* args[] = { (void*)&x4, (void*)&y4, (void*)&nt4, (void*)&n4 };
            launch_pdl((const void*)pin_kernel4, (n4 + 255) / 256, 256, args);
        }
        int rem = npins - n4 * 4;
        if (rem > 0) {
            int start = n4 * 4;
            void* args[] = { (void*)&pos, (void*)&p2n, (void*)&start, (void*)&npins };
            launch_pdl((const void*)pin_kernel_tail, (rem + 255) / 256, 256, args);
        }
    }

    // Phase 3: per-net HPWL + masked sum — PDL secondary
    {
        int nt = (nnets + 7) / 8;
        int blocks = (nt + 255) / 256;
        void* args[] = { (void*)&mask, (void*)&out, (void*)&nnets };
        launch_pdl((const void*)reduce_kernel, blocks, 256, args);
    }
}